// round 15
// baseline (speedup 1.0000x reference)
#include <cuda_runtime.h>
#include <cuda_fp16.h>
#include <math.h>
#include <stdint.h>

// ---------------- problem constants ----------------
#define NHR_MAX 100000
#define NHR_PAD 100096          // ceil(100000/128)*128
#define F_IN 256
#define F_W 512
#define IN_MSG 1024
#define LN_EPS 1e-5f

// scratch: fp16 activations (padded, K=512 everywhere), fp16 weights
__device__ __half g_a[(size_t)NHR_PAD * F_W];
__device__ __half g_b[(size_t)NHR_PAD * F_W];
__device__ __half g_w0[F_W * F_W];   // W0 cols 512..1023 only
__device__ __half g_w1[F_W * F_W];
__device__ __half g_w2[F_W * F_W];
__device__ __half g_w3[F_W * F_W];
__device__ float g_u[F_W], g_c1[F_W], g_r[F_W], g_c2[F_W];   // layer0 column vectors
__device__ float g_er[NHR_PAD], g_mu[NHR_PAD], g_rstd[NHR_PAD];
__device__ float g_es[8];            // SWe, Sbe, SWe2, SWebe, Sbe2
__device__ int g_idx_is64;

// ---------------- helpers ----------------
__device__ __forceinline__ uint32_t smem_u32(const void* p) {
    uint32_t a;
    asm("{ .reg .u64 t; cvta.to.shared.u64 t, %1; cvt.u32.u64 %0, t; }" : "=r"(a) : "l"(p));
    return a;
}
__device__ __forceinline__ float selu_f(float x) {
    const float sc = 1.0507009873554805f;
    const float al = 1.6732632423543772f;
    return x > 0.f ? sc * x : sc * al * expm1f(x);
}
__device__ __forceinline__ uint32_t f16x2_rn(float a, float b) {
    uint32_t r;
    asm("cvt.rn.f16x2.f32 %0, %1, %2;" : "=r"(r) : "f"(b), "f"(a));
    return r;
}
__device__ __forceinline__ void ldmatrix_x4(uint32_t& r0, uint32_t& r1, uint32_t& r2, uint32_t& r3,
                                            uint32_t addr) {
    asm volatile("ldmatrix.sync.aligned.m8n8.x4.shared.b16 {%0,%1,%2,%3}, [%4];"
                 : "=r"(r0), "=r"(r1), "=r"(r2), "=r"(r3) : "r"(addr));
}
__device__ __forceinline__ void mma_f16(float* d, const uint32_t* a, const uint32_t* b) {
    asm volatile(
        "mma.sync.aligned.m16n8k16.row.col.f32.f16.f16.f32 "
        "{%0,%1,%2,%3}, {%4,%5,%6,%7}, {%8,%9}, {%0,%1,%2,%3};"
        : "+f"(d[0]), "+f"(d[1]), "+f"(d[2]), "+f"(d[3])
        : "r"(a[0]), "r"(a[1]), "r"(a[2]), "r"(a[3]), "r"(b[0]), "r"(b[1]));
}
__device__ __forceinline__ void cp_async16(uint32_t dst, const void* src) {
    asm volatile("cp.async.cg.shared.global [%0], [%1], 16;"
                 :: "r"(dst), "l"(src) : "memory");
}
#define CP_COMMIT() asm volatile("cp.async.commit_group;" ::: "memory")
#define CP_WAIT2()  asm volatile("cp.async.wait_group 2;" ::: "memory")

// ---------------- e_enc scalar stats: SWe, Sbe, SWe2, SWebe, Sbe2 --------------
__global__ void estat_kernel(const float* __restrict__ We, const float* __restrict__ be) {
    int tid = threadIdx.x;  // 512 threads
    float w = We[tid], b = be[tid];
    float vals[5] = { w, b, w * w, w * b, b * b };
    __shared__ float red[5][16];
#pragma unroll
    for (int q = 0; q < 5; q++) {
        float s = vals[q];
#pragma unroll
        for (int o = 16; o > 0; o >>= 1) s += __shfl_xor_sync(0xFFFFFFFFu, s, o);
        if ((tid & 31) == 0) red[q][tid >> 5] = s;
    }
    __syncthreads();
    if (tid < 5) {
        float s = 0.f;
#pragma unroll
        for (int i = 0; i < 16; i++) s += red[tid][i];
        g_es[tid] = s;
    }
}

// ---------------- layer0 column vectors: u, c1, r, c2 --------------------------
__global__ void precomp_kernel(const float* __restrict__ W0,
                               const float* __restrict__ We,
                               const float* __restrict__ be,
                               const float* __restrict__ ln_g,
                               const float* __restrict__ ln_b,
                               const float* __restrict__ b0) {
    int o = blockIdx.x;      // 512 blocks
    int tid = threadIdx.x;   // 256 threads
    const float* w = W0 + (size_t)o * IN_MSG;
    float su = 0.f, sc1 = 0.f, sr = 0.f, sc2 = 0.f;
    for (int j = tid; j < IN_MSG; j += 256) {
        float wv = w[j];
        sr  += ln_g[j] * wv;
        sc2 += ln_b[j] * wv;
        if (j < F_W) {
            float gw = ln_g[j] * wv;
            su  += We[j] * gw;
            sc1 += be[j] * gw;
        }
    }
    __shared__ float red[4][8];
    float vals[4] = { su, sc1, sr, sc2 };
#pragma unroll
    for (int q = 0; q < 4; q++) {
        float s = vals[q];
#pragma unroll
        for (int off = 16; off > 0; off >>= 1) s += __shfl_xor_sync(0xFFFFFFFFu, s, off);
        if ((tid & 31) == 0) red[q][tid >> 5] = s;
    }
    __syncthreads();
    if (tid == 0) {
        float s0 = 0, s1 = 0, s2 = 0, s3 = 0;
#pragma unroll
        for (int i = 0; i < 8; i++) { s0 += red[0][i]; s1 += red[1][i]; s2 += red[2][i]; s3 += red[3][i]; }
        g_u[o] = s0; g_c1[o] = s1; g_r[o] = s2; g_c2[o] = s3 + b0[o];
    }
}

// ---------------- idx detect + weight converts (W0: cols 512..1023) ------------
__global__ void wconv_all_kernel(const int* __restrict__ idx32,
                                 const float* __restrict__ W0, __half* __restrict__ w0,
                                 const float* __restrict__ W1, __half* __restrict__ w1,
                                 const float* __restrict__ W2, __half* __restrict__ w2,
                                 const float* __restrict__ W3, __half* __restrict__ w3) {
    if (blockIdx.x == 0 && threadIdx.x == 0) {
        int allzero = 1;
        for (int i = 1; i < 128; i += 2)
            if (idx32[i] != 0) { allzero = 0; break; }
        g_idx_is64 = allzero;
    }
    const int n1 = F_W * F_W;
    int i = blockIdx.x * blockDim.x + threadIdx.x;
    if (i >= 4 * n1) return;
    if (i < n1) {
        int o = i >> 9, j = i & 511;
        w0[i] = __float2half_rn(W0[(o << 10) + F_W + j]);
    }
    else if (i < 2 * n1) w1[i - n1]     = __float2half_rn(W1[i - n1]);
    else if (i < 3 * n1) w2[i - 2 * n1] = __float2half_rn(W2[i - 2 * n1]);
    else                 w3[i - 3 * n1] = __float2half_rn(W3[i - 3 * n1]);
}

// ---------------- prep: warp-per-row gather + LN stats + fp16 pack -------------
__global__ void __launch_bounds__(256)
prep_kernel(const float* __restrict__ v,
            const float* __restrict__ e_rel,
            const void*  __restrict__ idx_raw,
            const float* __restrict__ v_skip,
            const float* __restrict__ ln_g,
            int M) {
    int wid = threadIdx.x >> 5, lid = threadIdx.x & 31;
    int row = blockIdx.x * 8 + wid;

    __half* oh = g_a + (size_t)row * F_W;

    if (row >= M) {  // padded tail
        uint4 z = make_uint4(0, 0, 0, 0);
        *(uint4*)(oh + lid * 8) = z;
        *(uint4*)(oh + 256 + lid * 8) = z;
        if (lid == 0) { g_er[row] = 0.f; g_mu[row] = 0.f; g_rstd[row] = 0.f; }
        return;
    }

    long long src;
    if (g_idx_is64) src = ((const long long*)idx_raw)[row];
    else            src = (long long)(((const int*)idx_raw)[row]);

    float er = e_rel[row];

    const float* vp = v + src * F_IN + lid * 8;
    const float* sp = v_skip + (size_t)row * F_IN + lid * 8;
    float4 a0 = *(const float4*)(vp);
    float4 a1 = *(const float4*)(vp + 4);
    float4 b0 = *(const float4*)(sp);
    float4 b1 = *(const float4*)(sp + 4);

    float s  = a0.x + a0.y + a0.z + a0.w + a1.x + a1.y + a1.z + a1.w
             + b0.x + b0.y + b0.z + b0.w + b1.x + b1.y + b1.z + b1.w;
    float s2 = a0.x*a0.x + a0.y*a0.y + a0.z*a0.z + a0.w*a0.w
             + a1.x*a1.x + a1.y*a1.y + a1.z*a1.z + a1.w*a1.w
             + b0.x*b0.x + b0.y*b0.y + b0.z*b0.z + b0.w*b0.w
             + b1.x*b1.x + b1.y*b1.y + b1.z*b1.z + b1.w*b1.w;
#pragma unroll
    for (int o = 16; o > 0; o >>= 1) {
        s  += __shfl_xor_sync(0xFFFFFFFFu, s,  o);
        s2 += __shfl_xor_sync(0xFFFFFFFFu, s2, o);
    }

    float SWe = g_es[0], Sbe = g_es[1], SWe2 = g_es[2], SWebe = g_es[3], Sbe2 = g_es[4];
    float sum   = s  + (-er * SWe + Sbe);
    float sumsq = s2 + (er * er * SWe2 - 2.f * er * SWebe + Sbe2);

    float mu   = sum * (1.0f / IN_MSG);
    float var  = sumsq * (1.0f / IN_MSG) - mu * mu;
    float rstd = rsqrtf(var + LN_EPS);

    const float* g0p = ln_g + F_W + lid * 8;
    const float* g1p = ln_g + F_W + F_IN + lid * 8;
    float4 ga0 = *(const float4*)(g0p);
    float4 ga1 = *(const float4*)(g0p + 4);
    float4 gb0 = *(const float4*)(g1p);
    float4 gb1 = *(const float4*)(g1p + 4);

    uint4 o0, o1;
    o0.x = f16x2_rn(a0.x * ga0.x, a0.y * ga0.y);
    o0.y = f16x2_rn(a0.z * ga0.z, a0.w * ga0.w);
    o0.z = f16x2_rn(a1.x * ga1.x, a1.y * ga1.y);
    o0.w = f16x2_rn(a1.z * ga1.z, a1.w * ga1.w);
    o1.x = f16x2_rn(b0.x * gb0.x, b0.y * gb0.y);
    o1.y = f16x2_rn(b0.z * gb0.z, b0.w * gb0.w);
    o1.z = f16x2_rn(b1.x * gb1.x, b1.y * gb1.y);
    o1.w = f16x2_rn(b1.z * gb1.z, b1.w * gb1.w);
    *(uint4*)(oh + lid * 8) = o0;
    *(uint4*)(oh + 256 + lid * 8) = o1;

    if (lid == 0) { g_er[row] = er; g_mu[row] = mu; g_rstd[row] = rstd; }
}

// ---------------- fp16 GEMM: CTA 128x64, 3 CTAs/SM, 4-stage, wait2 -------------
// layer0 (u != null): out = selu(rstd_i*(acc - er_i*u + c1 - mu_i*r) + c2)
// else:               out = selu(acc + bias)
#define BM 128
#define BN 64
#define BK 32
#define STAGES 4

#define PITCH 80
#define T_A 0
#define T_B 10240
#define STAGE_B 15360
#define GEMM_SMEM (STAGES * STAGE_B)

__global__ void __launch_bounds__(256, 3)
gemm_f16_selu(const __half* __restrict__ A,
              const __half* __restrict__ W,
              const float* __restrict__ bias,
              __half* __restrict__ Ch,
              float* __restrict__ Cf,
              const float* __restrict__ u,
              const float* __restrict__ c1v,
              const float* __restrict__ rv,
              const float* __restrict__ c2v,
              int M, int K) {
    extern __shared__ char smem[];
    uint32_t sb = smem_u32(smem);

    int tid = threadIdx.x;
    int wid = tid >> 5, lid = tid & 31;
    int warp_m = wid & 3;          // 0..3 -> 32 rows
    int warp_n = wid >> 2;         // 0..1 -> 32 cols
    int bm = blockIdx.y * BM;
    int bn = blockIdx.x * BN;

    // cp.async A: (row = tid/2, 32B half); B: (row = tid/4, 16B quarter)
    int a_row = tid >> 1, a_half = tid & 1;
    int b_row = tid >> 2, b_q    = tid & 3;
    const char* a_src = (const char*)(A + (size_t)(bm + a_row) * K) + a_half * 32;
    const char* b_src = (const char*)(W + (size_t)(bn + b_row) * K) + b_q * 16;
    uint32_t a_dst_off = (uint32_t)(a_row * PITCH + a_half * 32);
    uint32_t b_dst_off = (uint32_t)(b_row * PITCH + b_q * 16);

    float acc[2][4][4];
#pragma unroll
    for (int i = 0; i < 2; i++)
#pragma unroll
        for (int j = 0; j < 4; j++)
#pragma unroll
            for (int q = 0; q < 4; q++) acc[i][j][q] = 0.f;

    int a_lrow = warp_m * 32 + (lid & 15);
    int a_lchk = (lid >> 4) * 16;
    uint32_t a_lm_off = (uint32_t)(a_lrow * PITCH + a_lchk);
    int b_lrow = warp_n * 32 + (lid & 7) + ((lid >> 4) << 3);
    int b_lchk = ((lid >> 3) & 1) * 16;
    uint32_t b_lm_off = (uint32_t)(b_lrow * PITCH + b_lchk);

    const int S = K / BK;

    // prologue: stages 0..2. Note B cp.async covers a 32B k-slice per row pair via 2 quarters:
    // quarters 0,1 -> k bytes [0,32); quarters 2,3 -> [32,64). Each stage needs k-slice of 64B.
#pragma unroll
    for (int s = 0; s < STAGES - 1; s++) {
        int kb = s * BK * 2;
        uint32_t dst = sb + s * STAGE_B;
        cp_async16(dst + T_A + a_dst_off,      a_src + kb);
        cp_async16(dst + T_A + a_dst_off + 16, a_src + kb + 16);
        cp_async16(dst + T_B + b_dst_off,      b_src + kb);
        CP_COMMIT();
    }

    uint32_t tile_cur = sb;
    uint32_t dst_issue = sb + (STAGES - 1) * STAGE_B;
    int kb_issue = (STAGES - 1) * BK * 2;
    const int kb_end = S * BK * 2;

#pragma unroll 1
    for (int s = 0; s < S; s++) {
        CP_WAIT2();
        __syncthreads();

#pragma unroll
        for (int kk = 0; kk < 2; kk++) {
            uint32_t koff = kk * 32;
            uint32_t af[2][4];
#pragma unroll
            for (int mf = 0; mf < 2; mf++) {
                uint32_t ad = tile_cur + T_A + a_lm_off + mf * (16 * PITCH) + koff;
                ldmatrix_x4(af[mf][0], af[mf][1], af[mf][2], af[mf][3], ad);
            }
            uint32_t bf[4][2];
#pragma unroll
            for (int g = 0; g < 2; g++) {
                uint32_t bd = tile_cur + T_B + b_lm_off + g * (16 * PITCH) + koff;
                ldmatrix_x4(bf[g*2][0], bf[g*2][1], bf[g*2+1][0], bf[g*2+1][1], bd);
            }
#pragma unroll
            for (int mf = 0; mf < 2; mf++)
#pragma unroll
                for (int nf = 0; nf < 4; nf++)
                    mma_f16(acc[mf][nf], af[mf], bf[nf]);
        }

        if (kb_issue < kb_end) {
            uint32_t dst = dst_issue;
            cp_async16(dst + T_A + a_dst_off,      a_src + kb_issue);
            cp_async16(dst + T_A + a_dst_off + 16, a_src + kb_issue + 16);
            cp_async16(dst + T_B + b_dst_off,      b_src + kb_issue);
        }
        CP_COMMIT();
        kb_issue += BK * 2;

        tile_cur += STAGE_B;
        if (tile_cur == sb + STAGES * STAGE_B) tile_cur = sb;
        dst_issue += STAGE_B;
        if (dst_issue == sb + STAGES * STAGE_B) dst_issue = sb;
    }

    int tig = lid & 3, grp = lid >> 2;

    if (u) {
        float erv[2][2], muv[2][2], rsv[2][2];
#pragma unroll
        for (int mf = 0; mf < 2; mf++)
#pragma unroll
            for (int half = 0; half < 2; half++) {
                int row = bm + warp_m * 32 + mf * 16 + grp + half * 8;
                erv[mf][half] = g_er[row];
                muv[mf][half] = g_mu[row];
                rsv[mf][half] = g_rstd[row];
            }
#pragma unroll
        for (int nf = 0; nf < 4; nf++) {
            int col = bn + warp_n * 32 + nf * 8 + tig * 2;
            float u0 = u[col],  u1 = u[col + 1];
            float a0 = c1v[col], a1 = c1v[col + 1];
            float r0 = rv[col],  r1 = rv[col + 1];
            float d0 = c2v[col], d1 = c2v[col + 1];
#pragma unroll
            for (int mf = 0; mf < 2; mf++)
#pragma unroll
                for (int half = 0; half < 2; half++) {
                    int row = bm + warp_m * 32 + mf * 16 + grp + half * 8;
                    float e = erv[mf][half], m = muv[mf][half], rs = rsv[mf][half];
                    float o0 = selu_f(rs * (acc[mf][nf][half*2+0] - e * u0 + a0 - m * r0) + d0);
                    float o1 = selu_f(rs * (acc[mf][nf][half*2+1] - e * u1 + a1 - m * r1) + d1);
                    size_t off = (size_t)row * F_W + col;
                    *(uint32_t*)((char*)Ch + off * 2) = f16x2_rn(o0, o1);
                }
        }
    } else {
#pragma unroll
        for (int nf = 0; nf < 4; nf++) {
            int col = bn + warp_n * 32 + nf * 8 + tig * 2;
            float bz0 = bias[col], bz1 = bias[col + 1];
#pragma unroll
            for (int mf = 0; mf < 2; mf++) {
                int row0 = bm + warp_m * 32 + mf * 16 + grp;
#pragma unroll
                for (int half = 0; half < 2; half++) {
                    int row = row0 + half * 8;
                    float o0 = selu_f(acc[mf][nf][half * 2 + 0] + bz0);
                    float o1 = selu_f(acc[mf][nf][half * 2 + 1] + bz1);
                    size_t off = (size_t)row * F_W + col;
                    if (Cf) {
                        if (row < M) *(float2*)(Cf + off) = make_float2(o0, o1);
                    } else {
                        *(uint32_t*)((char*)Ch + off * 2) = f16x2_rn(o0, o1);
                    }
                }
            }
        }
    }
}

// ---------------- launch ----------------
extern "C" void kernel_launch(void* const* d_in, const int* in_sizes, int n_in,
                              void* d_out, int out_size) {
    const float* v      = (const float*)d_in[0];
    const float* e_rel  = (const float*)d_in[1];
    const void*  idx    = (const void*) d_in[2];
    const float* v_skip = (const float*)d_in[3];
    const float* We     = (const float*)d_in[4];
    const float* be     = (const float*)d_in[5];
    const float* ln_g   = (const float*)d_in[6];
    const float* ln_b   = (const float*)d_in[7];
    const float* W0     = (const float*)d_in[8];
    const float* b0     = (const float*)d_in[9];
    const float* W1     = (const float*)d_in[10];
    const float* b1     = (const float*)d_in[11];
    const float* W2     = (const float*)d_in[12];
    const float* b2     = (const float*)d_in[13];
    const float* W3     = (const float*)d_in[14];
    const float* b3     = (const float*)d_in[15];

    int M = in_sizes[1];  // e_rel element count = N_HR

    __half *a, *b, *w0, *w1, *w2, *w3;
    float *pu, *pc1, *pr, *pc2;
    cudaGetSymbolAddress((void**)&a,  g_a);
    cudaGetSymbolAddress((void**)&b,  g_b);
    cudaGetSymbolAddress((void**)&w0, g_w0);
    cudaGetSymbolAddress((void**)&w1, g_w1);
    cudaGetSymbolAddress((void**)&w2, g_w2);
    cudaGetSymbolAddress((void**)&w3, g_w3);
    cudaGetSymbolAddress((void**)&pu,  g_u);
    cudaGetSymbolAddress((void**)&pc1, g_c1);
    cudaGetSymbolAddress((void**)&pr,  g_r);
    cudaGetSymbolAddress((void**)&pc2, g_c2);

    cudaFuncSetAttribute(gemm_f16_selu,
                         cudaFuncAttributeMaxDynamicSharedMemorySize, GEMM_SMEM);

    int ntot = 4 * F_W * F_W;
    int mpad = ((M + BM - 1) / BM) * BM;
    dim3 grid(F_W / BN, mpad / BM);

    estat_kernel<<<1, 512>>>(We, be);
    wconv_all_kernel<<<(ntot + 255) / 256, 256>>>((const int*)idx,
                                                  W0, w0, W1, w1, W2, w2, W3, w3);
    precomp_kernel<<<512, 256>>>(W0, We, be, ln_g, ln_b, b0);
    prep_kernel<<<mpad / 8, 256>>>(v, e_rel, idx, v_skip, ln_g, M);

    gemm_f16_selu<<<grid, 256, GEMM_SMEM>>>(a, w0, nullptr, b, nullptr,
                                            pu, pc1, pr, pc2, M, F_W);
    gemm_f16_selu<<<grid, 256, GEMM_SMEM>>>(b, w1, b1, a, nullptr,
                                            nullptr, nullptr, nullptr, nullptr, M, F_W);
    gemm_f16_selu<<<grid, 256, GEMM_SMEM>>>(a, w2, b2, b, nullptr,
                                            nullptr, nullptr, nullptr, nullptr, M, F_W);
    gemm_f16_selu<<<grid, 256, GEMM_SMEM>>>(b, w3, b3, nullptr, (float*)d_out,
                                            nullptr, nullptr, nullptr, nullptr, M, F_W);
}

// round 16
// speedup vs baseline: 1.0630x; 1.0630x over previous
#include <cuda_runtime.h>
#include <cuda_fp16.h>
#include <math.h>
#include <stdint.h>

// ---------------- problem constants ----------------
#define NHR_MAX 100000
#define NHR_PAD 100096          // ceil(100000/128)*128
#define F_IN 256
#define F_W 512
#define IN_MSG 1024
#define LN_EPS 1e-5f

// scratch: fp16 activations (padded, K=512 everywhere), fp16 weights
__device__ __half g_a[(size_t)NHR_PAD * F_W];
__device__ __half g_b[(size_t)NHR_PAD * F_W];
__device__ __half g_w0[F_W * F_W];   // W0 cols 512..1023 only
__device__ __half g_w1[F_W * F_W];
__device__ __half g_w2[F_W * F_W];
__device__ __half g_w3[F_W * F_W];
__device__ float g_u[F_W], g_c1[F_W], g_r[F_W], g_c2[F_W];   // layer0 column vectors
__device__ float g_er[NHR_PAD], g_mu[NHR_PAD], g_rstd[NHR_PAD];
__device__ float g_es[8];            // SWe, Sbe, SWe2, SWebe, Sbe2
__device__ int g_idx_is64;

// ---------------- helpers ----------------
__device__ __forceinline__ uint32_t smem_u32(const void* p) {
    uint32_t a;
    asm("{ .reg .u64 t; cvta.to.shared.u64 t, %1; cvt.u32.u64 %0, t; }" : "=r"(a) : "l"(p));
    return a;
}
__device__ __forceinline__ float selu_f(float x) {
    const float sc = 1.0507009873554805f;
    const float al = 1.6732632423543772f;
    return x > 0.f ? sc * x : sc * al * expm1f(x);
}
__device__ __forceinline__ uint32_t f16x2_rn(float a, float b) {
    uint32_t r;
    asm("cvt.rn.f16x2.f32 %0, %1, %2;" : "=r"(r) : "f"(b), "f"(a));
    return r;
}
__device__ __forceinline__ void ldmatrix_x4(uint32_t& r0, uint32_t& r1, uint32_t& r2, uint32_t& r3,
                                            uint32_t addr) {
    asm volatile("ldmatrix.sync.aligned.m8n8.x4.shared.b16 {%0,%1,%2,%3}, [%4];"
                 : "=r"(r0), "=r"(r1), "=r"(r2), "=r"(r3) : "r"(addr));
}
__device__ __forceinline__ void mma_f16(float* d, const uint32_t* a, const uint32_t* b) {
    asm volatile(
        "mma.sync.aligned.m16n8k16.row.col.f32.f16.f16.f32 "
        "{%0,%1,%2,%3}, {%4,%5,%6,%7}, {%8,%9}, {%0,%1,%2,%3};"
        : "+f"(d[0]), "+f"(d[1]), "+f"(d[2]), "+f"(d[3])
        : "r"(a[0]), "r"(a[1]), "r"(a[2]), "r"(a[3]), "r"(b[0]), "r"(b[1]));
}
__device__ __forceinline__ void cp_async16(uint32_t dst, const void* src) {
    asm volatile("cp.async.cg.shared.global [%0], [%1], 16;"
                 :: "r"(dst), "l"(src) : "memory");
}
#define CP_COMMIT() asm volatile("cp.async.commit_group;" ::: "memory")
#define CP_WAIT2()  asm volatile("cp.async.wait_group 2;" ::: "memory")

// ---------------- idx detect + estat + weight converts -------------------------
// block 0 additionally computes e_enc scalar stats (512 elems, 2 per thread).
__global__ void wconv_all_kernel(const int* __restrict__ idx32,
                                 const float* __restrict__ We,
                                 const float* __restrict__ be,
                                 const float* __restrict__ W0, __half* __restrict__ w0,
                                 const float* __restrict__ W1, __half* __restrict__ w1,
                                 const float* __restrict__ W2, __half* __restrict__ w2,
                                 const float* __restrict__ W3, __half* __restrict__ w3) {
    int tid = threadIdx.x;
    if (blockIdx.x == 0) {
        if (tid == 0) {
            int allzero = 1;
            for (int i = 1; i < 128; i += 2)
                if (idx32[i] != 0) { allzero = 0; break; }
            g_idx_is64 = allzero;
        }
        // estat: sums over 512 elems, each of 256 threads takes 2
        float w0v = We[tid], b0v = be[tid];
        float w1v = We[tid + 256], b1v = be[tid + 256];
        float vals[5] = { w0v + w1v, b0v + b1v,
                          w0v * w0v + w1v * w1v,
                          w0v * b0v + w1v * b1v,
                          b0v * b0v + b1v * b1v };
        __shared__ float red[5][8];
#pragma unroll
        for (int q = 0; q < 5; q++) {
            float s = vals[q];
#pragma unroll
            for (int o = 16; o > 0; o >>= 1) s += __shfl_xor_sync(0xFFFFFFFFu, s, o);
            if ((tid & 31) == 0) red[q][tid >> 5] = s;
        }
        __syncthreads();
        if (tid < 5) {
            float s = 0.f;
#pragma unroll
            for (int i = 0; i < 8; i++) s += red[tid][i];
            g_es[tid] = s;
        }
    }
    const int n1 = F_W * F_W;
    int i = blockIdx.x * blockDim.x + tid;
    if (i >= 4 * n1) return;
    if (i < n1) {
        int o = i >> 9, j = i & 511;
        w0[i] = __float2half_rn(W0[(o << 10) + F_W + j]);
    }
    else if (i < 2 * n1) w1[i - n1]     = __float2half_rn(W1[i - n1]);
    else if (i < 3 * n1) w2[i - 2 * n1] = __float2half_rn(W2[i - 2 * n1]);
    else                 w3[i - 3 * n1] = __float2half_rn(W3[i - 3 * n1]);
}

// ---------------- layer0 column vectors: u, c1, r, c2 --------------------------
__global__ void precomp_kernel(const float* __restrict__ W0,
                               const float* __restrict__ We,
                               const float* __restrict__ be,
                               const float* __restrict__ ln_g,
                               const float* __restrict__ ln_b,
                               const float* __restrict__ b0) {
    int o = blockIdx.x;      // 512 blocks
    int tid = threadIdx.x;   // 256 threads
    const float* w = W0 + (size_t)o * IN_MSG;
    float su = 0.f, sc1 = 0.f, sr = 0.f, sc2 = 0.f;
    for (int j = tid; j < IN_MSG; j += 256) {
        float wv = w[j];
        sr  += ln_g[j] * wv;
        sc2 += ln_b[j] * wv;
        if (j < F_W) {
            float gw = ln_g[j] * wv;
            su  += We[j] * gw;
            sc1 += be[j] * gw;
        }
    }
    __shared__ float red[4][8];
    float vals[4] = { su, sc1, sr, sc2 };
#pragma unroll
    for (int q = 0; q < 4; q++) {
        float s = vals[q];
#pragma unroll
        for (int off = 16; off > 0; off >>= 1) s += __shfl_xor_sync(0xFFFFFFFFu, s, off);
        if ((tid & 31) == 0) red[q][tid >> 5] = s;
    }
    __syncthreads();
    if (tid == 0) {
        float s0 = 0, s1 = 0, s2 = 0, s3 = 0;
#pragma unroll
        for (int i = 0; i < 8; i++) { s0 += red[0][i]; s1 += red[1][i]; s2 += red[2][i]; s3 += red[3][i]; }
        g_u[o] = s0; g_c1[o] = s1; g_r[o] = s2; g_c2[o] = s3 + b0[o];
    }
}

// ---------------- prep: warp-per-row gather + LN stats + fp16 pack -------------
__global__ void __launch_bounds__(256)
prep_kernel(const float* __restrict__ v,
            const float* __restrict__ e_rel,
            const void*  __restrict__ idx_raw,
            const float* __restrict__ v_skip,
            const float* __restrict__ ln_g,
            int M) {
    int wid = threadIdx.x >> 5, lid = threadIdx.x & 31;
    int row = blockIdx.x * 8 + wid;

    __half* oh = g_a + (size_t)row * F_W;

    if (row >= M) {  // padded tail
        uint4 z = make_uint4(0, 0, 0, 0);
        *(uint4*)(oh + lid * 8) = z;
        *(uint4*)(oh + 256 + lid * 8) = z;
        if (lid == 0) { g_er[row] = 0.f; g_mu[row] = 0.f; g_rstd[row] = 0.f; }
        return;
    }

    long long src;
    if (g_idx_is64) src = ((const long long*)idx_raw)[row];
    else            src = (long long)(((const int*)idx_raw)[row]);

    float er = e_rel[row];

    const float* vp = v + src * F_IN + lid * 8;
    const float* sp = v_skip + (size_t)row * F_IN + lid * 8;
    float4 a0 = *(const float4*)(vp);
    float4 a1 = *(const float4*)(vp + 4);
    float4 b0 = *(const float4*)(sp);
    float4 b1 = *(const float4*)(sp + 4);

    float s  = a0.x + a0.y + a0.z + a0.w + a1.x + a1.y + a1.z + a1.w
             + b0.x + b0.y + b0.z + b0.w + b1.x + b1.y + b1.z + b1.w;
    float s2 = a0.x*a0.x + a0.y*a0.y + a0.z*a0.z + a0.w*a0.w
             + a1.x*a1.x + a1.y*a1.y + a1.z*a1.z + a1.w*a1.w
             + b0.x*b0.x + b0.y*b0.y + b0.z*b0.z + b0.w*b0.w
             + b1.x*b1.x + b1.y*b1.y + b1.z*b1.z + b1.w*b1.w;
#pragma unroll
    for (int o = 16; o > 0; o >>= 1) {
        s  += __shfl_xor_sync(0xFFFFFFFFu, s,  o);
        s2 += __shfl_xor_sync(0xFFFFFFFFu, s2, o);
    }

    float SWe = g_es[0], Sbe = g_es[1], SWe2 = g_es[2], SWebe = g_es[3], Sbe2 = g_es[4];
    float sum   = s  + (-er * SWe + Sbe);
    float sumsq = s2 + (er * er * SWe2 - 2.f * er * SWebe + Sbe2);

    float mu   = sum * (1.0f / IN_MSG);
    float var  = sumsq * (1.0f / IN_MSG) - mu * mu;
    float rstd = rsqrtf(var + LN_EPS);

    const float* g0p = ln_g + F_W + lid * 8;
    const float* g1p = ln_g + F_W + F_IN + lid * 8;
    float4 ga0 = *(const float4*)(g0p);
    float4 ga1 = *(const float4*)(g0p + 4);
    float4 gb0 = *(const float4*)(g1p);
    float4 gb1 = *(const float4*)(g1p + 4);

    uint4 o0, o1;
    o0.x = f16x2_rn(a0.x * ga0.x, a0.y * ga0.y);
    o0.y = f16x2_rn(a0.z * ga0.z, a0.w * ga0.w);
    o0.z = f16x2_rn(a1.x * ga1.x, a1.y * ga1.y);
    o0.w = f16x2_rn(a1.z * ga1.z, a1.w * ga1.w);
    o1.x = f16x2_rn(b0.x * gb0.x, b0.y * gb0.y);
    o1.y = f16x2_rn(b0.z * gb0.z, b0.w * gb0.w);
    o1.z = f16x2_rn(b1.x * gb1.x, b1.y * gb1.y);
    o1.w = f16x2_rn(b1.z * gb1.z, b1.w * gb1.w);
    *(uint4*)(oh + lid * 8) = o0;
    *(uint4*)(oh + 256 + lid * 8) = o1;

    if (lid == 0) { g_er[row] = er; g_mu[row] = mu; g_rstd[row] = rstd; }
}

// ---------------- fp16 GEMM (R14 config; mid-compute cp.async issue) -----------
// layer0 (u != null): out = selu(rstd_i*(acc - er_i*u + c1 - mu_i*r) + c2)
// else:               out = selu(acc + bias)
#define BM 128
#define BN 128
#define BK 32
#define STAGES 4

#define PITCH 80
#define T_A 0
#define T_B 10240
#define STAGE_B 20480
#define GEMM_SMEM (STAGES * STAGE_B)

__global__ void __launch_bounds__(256, 2)
gemm_f16_selu(const __half* __restrict__ A,
              const __half* __restrict__ W,
              const float* __restrict__ bias,
              __half* __restrict__ Ch,
              float* __restrict__ Cf,
              const float* __restrict__ u,
              const float* __restrict__ c1v,
              const float* __restrict__ rv,
              const float* __restrict__ c2v,
              int M, int K) {
    extern __shared__ char smem[];
    uint32_t sb = smem_u32(smem);

    int tid = threadIdx.x;
    int wid = tid >> 5, lid = tid & 31;
    int warp_m = wid & 3;
    int warp_n = wid >> 2;
    int bm = blockIdx.y * BM;
    int bn = blockIdx.x * BN;

    int g_row  = tid >> 1;
    int g_half = tid & 1;
    const char* a_src = (const char*)(A + (size_t)(bm + g_row) * K) + g_half * 32;
    const char* b_src = (const char*)(W + (size_t)(bn + g_row) * K) + g_half * 32;
    uint32_t dst_off = (uint32_t)(g_row * PITCH + g_half * 32);

    float acc[2][8][4];
#pragma unroll
    for (int i = 0; i < 2; i++)
#pragma unroll
        for (int j = 0; j < 8; j++)
#pragma unroll
            for (int q = 0; q < 4; q++) acc[i][j][q] = 0.f;

    int a_lrow = warp_m * 32 + (lid & 15);
    int a_lchk = (lid >> 4) * 16;
    uint32_t a_lm_off = (uint32_t)(a_lrow * PITCH + a_lchk);
    int b_lrow = warp_n * 64 + (lid & 7) + ((lid >> 4) << 3);
    int b_lchk = ((lid >> 3) & 1) * 16;
    uint32_t b_lm_off = (uint32_t)(b_lrow * PITCH + b_lchk);

    const int S = K / BK;

#pragma unroll
    for (int s = 0; s < STAGES - 1; s++) {
        int kb = s * BK * 2;
        uint32_t dst = sb + s * STAGE_B + dst_off;
        cp_async16(dst + T_A,      a_src + kb);
        cp_async16(dst + T_A + 16, a_src + kb + 16);
        cp_async16(dst + T_B,      b_src + kb);
        cp_async16(dst + T_B + 16, b_src + kb + 16);
        CP_COMMIT();
    }

    uint32_t tile_cur = sb;
    uint32_t dst_issue = sb + (STAGES - 1) * STAGE_B;
    int kb_issue = (STAGES - 1) * BK * 2;
    const int kb_end = S * BK * 2;

#pragma unroll 1
    for (int s = 0; s < S; s++) {
        CP_WAIT2();
        __syncthreads();

        // ---- kk = 0: LDSM + MMA ----
        {
            uint32_t af[2][4];
#pragma unroll
            for (int mf = 0; mf < 2; mf++) {
                uint32_t ad = tile_cur + T_A + a_lm_off + mf * (16 * PITCH);
                ldmatrix_x4(af[mf][0], af[mf][1], af[mf][2], af[mf][3], ad);
            }
            uint32_t bf[8][2];
#pragma unroll
            for (int g = 0; g < 4; g++) {
                uint32_t bd = tile_cur + T_B + b_lm_off + g * (16 * PITCH);
                ldmatrix_x4(bf[g*2][0], bf[g*2][1], bf[g*2+1][0], bf[g*2+1][1], bd);
            }
#pragma unroll
            for (int mf = 0; mf < 2; mf++)
#pragma unroll
                for (int nf = 0; nf < 8; nf++)
                    mma_f16(acc[mf][nf], af[mf], bf[nf]);
        }

        // ---- mid-compute issue of stage s+3 (tensor pipe busy with kk=0 MMAs) ----
        if (kb_issue < kb_end) {
            uint32_t dst = dst_issue + dst_off;
            cp_async16(dst + T_A,      a_src + kb_issue);
            cp_async16(dst + T_A + 16, a_src + kb_issue + 16);
            cp_async16(dst + T_B,      b_src + kb_issue);
            cp_async16(dst + T_B + 16, b_src + kb_issue + 16);
        }
        CP_COMMIT();
        kb_issue += BK * 2;

        // ---- kk = 1: LDSM + MMA ----
        {
            uint32_t af[2][4];
#pragma unroll
            for (int mf = 0; mf < 2; mf++) {
                uint32_t ad = tile_cur + T_A + a_lm_off + mf * (16 * PITCH) + 32;
                ldmatrix_x4(af[mf][0], af[mf][1], af[mf][2], af[mf][3], ad);
            }
            uint32_t bf[8][2];
#pragma unroll
            for (int g = 0; g < 4; g++) {
                uint32_t bd = tile_cur + T_B + b_lm_off + g * (16 * PITCH) + 32;
                ldmatrix_x4(bf[g*2][0], bf[g*2][1], bf[g*2+1][0], bf[g*2+1][1], bd);
            }
#pragma unroll
            for (int mf = 0; mf < 2; mf++)
#pragma unroll
                for (int nf = 0; nf < 8; nf++)
                    mma_f16(acc[mf][nf], af[mf], bf[nf]);
        }

        tile_cur += STAGE_B;
        if (tile_cur == sb + STAGES * STAGE_B) tile_cur = sb;
        dst_issue += STAGE_B;
        if (dst_issue == sb + STAGES * STAGE_B) dst_issue = sb;
    }

    int tig = lid & 3, grp = lid >> 2;

    if (u) {
        float erv[2][2], muv[2][2], rsv[2][2];
#pragma unroll
        for (int mf = 0; mf < 2; mf++)
#pragma unroll
            for (int half = 0; half < 2; half++) {
                int row = bm + warp_m * 32 + mf * 16 + grp + half * 8;
                erv[mf][half] = g_er[row];
                muv[mf][half] = g_mu[row];
                rsv[mf][half] = g_rstd[row];
            }
#pragma unroll
        for (int nf = 0; nf < 8; nf++) {
            int col = bn + warp_n * 64 + nf * 8 + tig * 2;
            float u0 = u[col],  u1 = u[col + 1];
            float a0 = c1v[col], a1 = c1v[col + 1];
            float r0 = rv[col],  r1 = rv[col + 1];
            float d0 = c2v[col], d1 = c2v[col + 1];
#pragma unroll
            for (int mf = 0; mf < 2; mf++)
#pragma unroll
                for (int half = 0; half < 2; half++) {
                    int row = bm + warp_m * 32 + mf * 16 + grp + half * 8;
                    float e = erv[mf][half], m = muv[mf][half], rs = rsv[mf][half];
                    float o0 = selu_f(rs * (acc[mf][nf][half*2+0] - e * u0 + a0 - m * r0) + d0);
                    float o1 = selu_f(rs * (acc[mf][nf][half*2+1] - e * u1 + a1 - m * r1) + d1);
                    size_t off = (size_t)row * F_W + col;
                    *(uint32_t*)((char*)Ch + off * 2) = f16x2_rn(o0, o1);
                }
        }
    } else {
#pragma unroll
        for (int nf = 0; nf < 8; nf++) {
            int col = bn + warp_n * 64 + nf * 8 + tig * 2;
            float bz0 = bias[col], bz1 = bias[col + 1];
#pragma unroll
            for (int mf = 0; mf < 2; mf++) {
                int row0 = bm + warp_m * 32 + mf * 16 + grp;
#pragma unroll
                for (int half = 0; half < 2; half++) {
                    int row = row0 + half * 8;
                    float o0 = selu_f(acc[mf][nf][half * 2 + 0] + bz0);
                    float o1 = selu_f(acc[mf][nf][half * 2 + 1] + bz1);
                    size_t off = (size_t)row * F_W + col;
                    if (Cf) {
                        if (row < M) *(float2*)(Cf + off) = make_float2(o0, o1);
                    } else {
                        *(uint32_t*)((char*)Ch + off * 2) = f16x2_rn(o0, o1);
                    }
                }
            }
        }
    }
}

// ---------------- launch ----------------
extern "C" void kernel_launch(void* const* d_in, const int* in_sizes, int n_in,
                              void* d_out, int out_size) {
    const float* v      = (const float*)d_in[0];
    const float* e_rel  = (const float*)d_in[1];
    const void*  idx    = (const void*) d_in[2];
    const float* v_skip = (const float*)d_in[3];
    const float* We     = (const float*)d_in[4];
    const float* be     = (const float*)d_in[5];
    const float* ln_g   = (const float*)d_in[6];
    const float* ln_b   = (const float*)d_in[7];
    const float* W0     = (const float*)d_in[8];
    const float* b0     = (const float*)d_in[9];
    const float* W1     = (const float*)d_in[10];
    const float* b1     = (const float*)d_in[11];
    const float* W2     = (const float*)d_in[12];
    const float* b2     = (const float*)d_in[13];
    const float* W3     = (const float*)d_in[14];
    const float* b3     = (const float*)d_in[15];

    int M = in_sizes[1];  // e_rel element count = N_HR

    __half *a, *b, *w0, *w1, *w2, *w3;
    float *pu, *pc1, *pr, *pc2;
    cudaGetSymbolAddress((void**)&a,  g_a);
    cudaGetSymbolAddress((void**)&b,  g_b);
    cudaGetSymbolAddress((void**)&w0, g_w0);
    cudaGetSymbolAddress((void**)&w1, g_w1);
    cudaGetSymbolAddress((void**)&w2, g_w2);
    cudaGetSymbolAddress((void**)&w3, g_w3);
    cudaGetSymbolAddress((void**)&pu,  g_u);
    cudaGetSymbolAddress((void**)&pc1, g_c1);
    cudaGetSymbolAddress((void**)&pr,  g_r);
    cudaGetSymbolAddress((void**)&pc2, g_c2);

    cudaFuncSetAttribute(gemm_f16_selu,
                         cudaFuncAttributeMaxDynamicSharedMemorySize, GEMM_SMEM);

    int ntot = 4 * F_W * F_W;
    int mpad = ((M + BM - 1) / BM) * BM;
    dim3 grid(F_W / BN, mpad / BM);

    wconv_all_kernel<<<(ntot + 255) / 256, 256>>>((const int*)idx, We, be,
                                                  W0, w0, W1, w1, W2, w2, W3, w3);
    precomp_kernel<<<512, 256>>>(W0, We, be, ln_g, ln_b, b0);
    prep_kernel<<<mpad / 8, 256>>>(v, e_rel, idx, v_skip, ln_g, M);

    gemm_f16_selu<<<grid, 256, GEMM_SMEM>>>(a, w0, nullptr, b, nullptr,
                                            pu, pc1, pr, pc2, M, F_W);
    gemm_f16_selu<<<grid, 256, GEMM_SMEM>>>(b, w1, b1, a, nullptr,
                                            nullptr, nullptr, nullptr, nullptr, M, F_W);
    gemm_f16_selu<<<grid, 256, GEMM_SMEM>>>(a, w2, b2, b, nullptr,
                                            nullptr, nullptr, nullptr, nullptr, M, F_W);
    gemm_f16_selu<<<grid, 256, GEMM_SMEM>>>(b, w3, b3, nullptr, (float*)d_out,
                                            nullptr, nullptr, nullptr, nullptr, M, F_W);
}

// round 17
// speedup vs baseline: 1.1044x; 1.0389x over previous
#include <cuda_runtime.h>
#include <cuda_fp16.h>
#include <math.h>
#include <stdint.h>

// ---------------- problem constants ----------------
#define NHR_MAX 100000
#define NHR_PAD 100096          // ceil(100000/128)*128
#define F_IN 256
#define F_W 512
#define IN_MSG 1024
#define LN_EPS 1e-5f

// scratch: fp16 activations (padded, K=512 everywhere), fp16 weights
__device__ __half g_a[(size_t)NHR_PAD * F_W];
__device__ __half g_b[(size_t)NHR_PAD * F_W];
__device__ __half g_w0[F_W * F_W];   // W0 cols 512..1023 only
__device__ __half g_w1[F_W * F_W];
__device__ __half g_w2[F_W * F_W];
__device__ __half g_w3[F_W * F_W];
__device__ float g_u[F_W], g_c1[F_W], g_r[F_W], g_c2[F_W];   // layer0 column vectors
__device__ float g_er[NHR_PAD], g_mu[NHR_PAD], g_rstd[NHR_PAD];
__device__ float g_es[8];            // SWe, Sbe, SWe2, SWebe, Sbe2
__device__ int g_idx_is64;

// ---------------- helpers ----------------
__device__ __forceinline__ uint32_t smem_u32(const void* p) {
    uint32_t a;
    asm("{ .reg .u64 t; cvta.to.shared.u64 t, %1; cvt.u32.u64 %0, t; }" : "=r"(a) : "l"(p));
    return a;
}
__device__ __forceinline__ float selu_f(float x) {
    const float sc = 1.0507009873554805f;
    const float al = 1.6732632423543772f;
    return x > 0.f ? sc * x : sc * al * expm1f(x);
}
__device__ __forceinline__ uint32_t f16x2_rn(float a, float b) {
    uint32_t r;
    asm("cvt.rn.f16x2.f32 %0, %1, %2;" : "=r"(r) : "f"(b), "f"(a));
    return r;
}
__device__ __forceinline__ void ldmatrix_x4(uint32_t& r0, uint32_t& r1, uint32_t& r2, uint32_t& r3,
                                            uint32_t addr) {
    asm volatile("ldmatrix.sync.aligned.m8n8.x4.shared.b16 {%0,%1,%2,%3}, [%4];"
                 : "=r"(r0), "=r"(r1), "=r"(r2), "=r"(r3) : "r"(addr));
}
__device__ __forceinline__ void mma_f16(float* d, const uint32_t* a, const uint32_t* b) {
    asm volatile(
        "mma.sync.aligned.m16n8k16.row.col.f32.f16.f16.f32 "
        "{%0,%1,%2,%3}, {%4,%5,%6,%7}, {%8,%9}, {%0,%1,%2,%3};"
        : "+f"(d[0]), "+f"(d[1]), "+f"(d[2]), "+f"(d[3])
        : "r"(a[0]), "r"(a[1]), "r"(a[2]), "r"(a[3]), "r"(b[0]), "r"(b[1]));
}
__device__ __forceinline__ void cp_async16(uint32_t dst, const void* src) {
    asm volatile("cp.async.cg.shared.global [%0], [%1], 16;"
                 :: "r"(dst), "l"(src) : "memory");
}
#define CP_COMMIT() asm volatile("cp.async.commit_group;" ::: "memory")
#define CP_WAIT2()  asm volatile("cp.async.wait_group 2;" ::: "memory")

// ---------------- idx detect + estat + weight converts -------------------------
__global__ void wconv_all_kernel(const int* __restrict__ idx32,
                                 const float* __restrict__ We,
                                 const float* __restrict__ be,
                                 const float* __restrict__ W0, __half* __restrict__ w0,
                                 const float* __restrict__ W1, __half* __restrict__ w1,
                                 const float* __restrict__ W2, __half* __restrict__ w2,
                                 const float* __restrict__ W3, __half* __restrict__ w3) {
    int tid = threadIdx.x;
    if (blockIdx.x == 0) {
        if (tid == 0) {
            int allzero = 1;
            for (int i = 1; i < 128; i += 2)
                if (idx32[i] != 0) { allzero = 0; break; }
            g_idx_is64 = allzero;
        }
        float w0v = We[tid], b0v = be[tid];
        float w1v = We[tid + 256], b1v = be[tid + 256];
        float vals[5] = { w0v + w1v, b0v + b1v,
                          w0v * w0v + w1v * w1v,
                          w0v * b0v + w1v * b1v,
                          b0v * b0v + b1v * b1v };
        __shared__ float red[5][8];
#pragma unroll
        for (int q = 0; q < 5; q++) {
            float s = vals[q];
#pragma unroll
            for (int o = 16; o > 0; o >>= 1) s += __shfl_xor_sync(0xFFFFFFFFu, s, o);
            if ((tid & 31) == 0) red[q][tid >> 5] = s;
        }
        __syncthreads();
        if (tid < 5) {
            float s = 0.f;
#pragma unroll
            for (int i = 0; i < 8; i++) s += red[tid][i];
            g_es[tid] = s;
        }
    }
    const int n1 = F_W * F_W;
    int i = blockIdx.x * blockDim.x + tid;
    if (i >= 4 * n1) return;
    if (i < n1) {
        int o = i >> 9, j = i & 511;
        w0[i] = __float2half_rn(W0[(o << 10) + F_W + j]);
    }
    else if (i < 2 * n1) w1[i - n1]     = __float2half_rn(W1[i - n1]);
    else if (i < 3 * n1) w2[i - 2 * n1] = __float2half_rn(W2[i - 2 * n1]);
    else                 w3[i - 3 * n1] = __float2half_rn(W3[i - 3 * n1]);
}

// ---------------- layer0 column vectors: u, c1, r, c2 --------------------------
__global__ void precomp_kernel(const float* __restrict__ W0,
                               const float* __restrict__ We,
                               const float* __restrict__ be,
                               const float* __restrict__ ln_g,
                               const float* __restrict__ ln_b,
                               const float* __restrict__ b0) {
    int o = blockIdx.x;      // 512 blocks
    int tid = threadIdx.x;   // 256 threads
    const float* w = W0 + (size_t)o * IN_MSG;
    float su = 0.f, sc1 = 0.f, sr = 0.f, sc2 = 0.f;
    for (int j = tid; j < IN_MSG; j += 256) {
        float wv = w[j];
        sr  += ln_g[j] * wv;
        sc2 += ln_b[j] * wv;
        if (j < F_W) {
            float gw = ln_g[j] * wv;
            su  += We[j] * gw;
            sc1 += be[j] * gw;
        }
    }
    __shared__ float red[4][8];
    float vals[4] = { su, sc1, sr, sc2 };
#pragma unroll
    for (int q = 0; q < 4; q++) {
        float s = vals[q];
#pragma unroll
        for (int off = 16; off > 0; off >>= 1) s += __shfl_xor_sync(0xFFFFFFFFu, s, off);
        if ((tid & 31) == 0) red[q][tid >> 5] = s;
    }
    __syncthreads();
    if (tid == 0) {
        float s0 = 0, s1 = 0, s2 = 0, s3 = 0;
#pragma unroll
        for (int i = 0; i < 8; i++) { s0 += red[0][i]; s1 += red[1][i]; s2 += red[2][i]; s3 += red[3][i]; }
        g_u[o] = s0; g_c1[o] = s1; g_r[o] = s2; g_c2[o] = s3 + b0[o];
    }
}

// ---------------- prep: 2 rows per warp (MLP=8), LN stats, fp16 pack -----------
__global__ void __launch_bounds__(256)
prep_kernel(const float* __restrict__ v,
            const float* __restrict__ e_rel,
            const void*  __restrict__ idx_raw,
            const float* __restrict__ v_skip,
            const float* __restrict__ ln_g,
            int M) {
    int wid = threadIdx.x >> 5, lid = threadIdx.x & 31;
    int row0 = blockIdx.x * 16 + wid * 2;

    // gamma vectors (shared by both rows)
    const float* g0p = ln_g + F_W + lid * 8;
    const float* g1p = ln_g + F_W + F_IN + lid * 8;
    float4 ga0 = *(const float4*)(g0p);
    float4 ga1 = *(const float4*)(g0p + 4);
    float4 gb0 = *(const float4*)(g1p);
    float4 gb1 = *(const float4*)(g1p + 4);

    float SWe = g_es[0], Sbe = g_es[1], SWe2 = g_es[2], SWebe = g_es[3], Sbe2 = g_es[4];

#pragma unroll
    for (int rr = 0; rr < 2; rr++) {
        int row = row0 + rr;
        __half* oh = g_a + (size_t)row * F_W;

        if (row >= M) {
            uint4 z = make_uint4(0, 0, 0, 0);
            *(uint4*)(oh + lid * 8) = z;
            *(uint4*)(oh + 256 + lid * 8) = z;
            if (lid == 0) { g_er[row] = 0.f; g_mu[row] = 0.f; g_rstd[row] = 0.f; }
            continue;
        }

        long long src;
        if (g_idx_is64) src = ((const long long*)idx_raw)[row];
        else            src = (long long)(((const int*)idx_raw)[row]);

        float er = e_rel[row];

        const float* vp = v + src * F_IN + lid * 8;
        const float* sp = v_skip + (size_t)row * F_IN + lid * 8;
        float4 a0 = *(const float4*)(vp);
        float4 a1 = *(const float4*)(vp + 4);
        float4 b0 = *(const float4*)(sp);
        float4 b1 = *(const float4*)(sp + 4);

        float s  = a0.x + a0.y + a0.z + a0.w + a1.x + a1.y + a1.z + a1.w
                 + b0.x + b0.y + b0.z + b0.w + b1.x + b1.y + b1.z + b1.w;
        float s2 = a0.x*a0.x + a0.y*a0.y + a0.z*a0.z + a0.w*a0.w
                 + a1.x*a1.x + a1.y*a1.y + a1.z*a1.z + a1.w*a1.w
                 + b0.x*b0.x + b0.y*b0.y + b0.z*b0.z + b0.w*b0.w
                 + b1.x*b1.x + b1.y*b1.y + b1.z*b1.z + b1.w*b1.w;
#pragma unroll
        for (int o = 16; o > 0; o >>= 1) {
            s  += __shfl_xor_sync(0xFFFFFFFFu, s,  o);
            s2 += __shfl_xor_sync(0xFFFFFFFFu, s2, o);
        }

        float sum   = s  + (-er * SWe + Sbe);
        float sumsq = s2 + (er * er * SWe2 - 2.f * er * SWebe + Sbe2);

        float mu   = sum * (1.0f / IN_MSG);
        float var  = sumsq * (1.0f / IN_MSG) - mu * mu;
        float rstd = rsqrtf(var + LN_EPS);

        uint4 o0, o1;
        o0.x = f16x2_rn(a0.x * ga0.x, a0.y * ga0.y);
        o0.y = f16x2_rn(a0.z * ga0.z, a0.w * ga0.w);
        o0.z = f16x2_rn(a1.x * ga1.x, a1.y * ga1.y);
        o0.w = f16x2_rn(a1.z * ga1.z, a1.w * ga1.w);
        o1.x = f16x2_rn(b0.x * gb0.x, b0.y * gb0.y);
        o1.y = f16x2_rn(b0.z * gb0.z, b0.w * gb0.w);
        o1.z = f16x2_rn(b1.x * gb1.x, b1.y * gb1.y);
        o1.w = f16x2_rn(b1.z * gb1.z, b1.w * gb1.w);
        *(uint4*)(oh + lid * 8) = o0;
        *(uint4*)(oh + 256 + lid * 8) = o1;

        if (lid == 0) { g_er[row] = er; g_mu[row] = mu; g_rstd[row] = rstd; }
    }
}

// ---------------- fp16 GEMM (R14-exact: 4-stage, wait2, issue-after-compute) ---
// layer0 (u != null): out = selu(rstd_i*(acc - er_i*u + c1 - mu_i*r) + c2)
// else:               out = selu(acc + bias)
#define BM 128
#define BN 128
#define BK 32
#define STAGES 4

#define PITCH 80
#define T_A 0
#define T_B 10240
#define STAGE_B 20480
#define GEMM_SMEM (STAGES * STAGE_B)

__global__ void __launch_bounds__(256, 2)
gemm_f16_selu(const __half* __restrict__ A,
              const __half* __restrict__ W,
              const float* __restrict__ bias,
              __half* __restrict__ Ch,
              float* __restrict__ Cf,
              const float* __restrict__ u,
              const float* __restrict__ c1v,
              const float* __restrict__ rv,
              const float* __restrict__ c2v,
              int M, int K) {
    extern __shared__ char smem[];
    uint32_t sb = smem_u32(smem);

    int tid = threadIdx.x;
    int wid = tid >> 5, lid = tid & 31;
    int warp_m = wid & 3;
    int warp_n = wid >> 2;
    int bm = blockIdx.y * BM;
    int bn = blockIdx.x * BN;

    int g_row  = tid >> 1;
    int g_half = tid & 1;
    const char* a_src = (const char*)(A + (size_t)(bm + g_row) * K) + g_half * 32;
    const char* b_src = (const char*)(W + (size_t)(bn + g_row) * K) + g_half * 32;
    uint32_t dst_off = (uint32_t)(g_row * PITCH + g_half * 32);

    float acc[2][8][4];
#pragma unroll
    for (int i = 0; i < 2; i++)
#pragma unroll
        for (int j = 0; j < 8; j++)
#pragma unroll
            for (int q = 0; q < 4; q++) acc[i][j][q] = 0.f;

    int a_lrow = warp_m * 32 + (lid & 15);
    int a_lchk = (lid >> 4) * 16;
    uint32_t a_lm_off = (uint32_t)(a_lrow * PITCH + a_lchk);
    int b_lrow = warp_n * 64 + (lid & 7) + ((lid >> 4) << 3);
    int b_lchk = ((lid >> 3) & 1) * 16;
    uint32_t b_lm_off = (uint32_t)(b_lrow * PITCH + b_lchk);

    const int S = K / BK;

#pragma unroll
    for (int s = 0; s < STAGES - 1; s++) {
        int kb = s * BK * 2;
        uint32_t dst = sb + s * STAGE_B + dst_off;
        cp_async16(dst + T_A,      a_src + kb);
        cp_async16(dst + T_A + 16, a_src + kb + 16);
        cp_async16(dst + T_B,      b_src + kb);
        cp_async16(dst + T_B + 16, b_src + kb + 16);
        CP_COMMIT();
    }

    uint32_t tile_cur = sb;
    uint32_t dst_issue = sb + (STAGES - 1) * STAGE_B;
    int kb_issue = (STAGES - 1) * BK * 2;
    const int kb_end = S * BK * 2;

#pragma unroll 1
    for (int s = 0; s < S; s++) {
        CP_WAIT2();
        __syncthreads();

#pragma unroll
        for (int kk = 0; kk < 2; kk++) {
            uint32_t koff = kk * 32;
            uint32_t af[2][4];
#pragma unroll
            for (int mf = 0; mf < 2; mf++) {
                uint32_t ad = tile_cur + T_A + a_lm_off + mf * (16 * PITCH) + koff;
                ldmatrix_x4(af[mf][0], af[mf][1], af[mf][2], af[mf][3], ad);
            }
            uint32_t bf[8][2];
#pragma unroll
            for (int g = 0; g < 4; g++) {
                uint32_t bd = tile_cur + T_B + b_lm_off + g * (16 * PITCH) + koff;
                ldmatrix_x4(bf[g*2][0], bf[g*2][1], bf[g*2+1][0], bf[g*2+1][1], bd);
            }
#pragma unroll
            for (int mf = 0; mf < 2; mf++)
#pragma unroll
                for (int nf = 0; nf < 8; nf++)
                    mma_f16(acc[mf][nf], af[mf], bf[nf]);
        }

        if (kb_issue < kb_end) {
            uint32_t dst = dst_issue + dst_off;
            cp_async16(dst + T_A,      a_src + kb_issue);
            cp_async16(dst + T_A + 16, a_src + kb_issue + 16);
            cp_async16(dst + T_B,      b_src + kb_issue);
            cp_async16(dst + T_B + 16, b_src + kb_issue + 16);
        }
        CP_COMMIT();
        kb_issue += BK * 2;

        tile_cur += STAGE_B;
        if (tile_cur == sb + STAGES * STAGE_B) tile_cur = sb;
        dst_issue += STAGE_B;
        if (dst_issue == sb + STAGES * STAGE_B) dst_issue = sb;
    }

    int tig = lid & 3, grp = lid >> 2;

    if (u) {
        float erv[2][2], muv[2][2], rsv[2][2];
#pragma unroll
        for (int mf = 0; mf < 2; mf++)
#pragma unroll
            for (int half = 0; half < 2; half++) {
                int row = bm + warp_m * 32 + mf * 16 + grp + half * 8;
                erv[mf][half] = g_er[row];
                muv[mf][half] = g_mu[row];
                rsv[mf][half] = g_rstd[row];
            }
#pragma unroll
        for (int nf = 0; nf < 8; nf++) {
            int col = bn + warp_n * 64 + nf * 8 + tig * 2;
            float u0 = u[col],  u1 = u[col + 1];
            float a0 = c1v[col], a1 = c1v[col + 1];
            float r0 = rv[col],  r1 = rv[col + 1];
            float d0 = c2v[col], d1 = c2v[col + 1];
#pragma unroll
            for (int mf = 0; mf < 2; mf++)
#pragma unroll
                for (int half = 0; half < 2; half++) {
                    int row = bm + warp_m * 32 + mf * 16 + grp + half * 8;
                    float e = erv[mf][half], m = muv[mf][half], rs = rsv[mf][half];
                    float o0 = selu_f(rs * (acc[mf][nf][half*2+0] - e * u0 + a0 - m * r0) + d0);
                    float o1 = selu_f(rs * (acc[mf][nf][half*2+1] - e * u1 + a1 - m * r1) + d1);
                    size_t off = (size_t)row * F_W + col;
                    *(uint32_t*)((char*)Ch + off * 2) = f16x2_rn(o0, o1);
                }
        }
    } else {
#pragma unroll
        for (int nf = 0; nf < 8; nf++) {
            int col = bn + warp_n * 64 + nf * 8 + tig * 2;
            float bz0 = bias[col], bz1 = bias[col + 1];
#pragma unroll
            for (int mf = 0; mf < 2; mf++) {
                int row0 = bm + warp_m * 32 + mf * 16 + grp;
#pragma unroll
                for (int half = 0; half < 2; half++) {
                    int row = row0 + half * 8;
                    float o0 = selu_f(acc[mf][nf][half * 2 + 0] + bz0);
                    float o1 = selu_f(acc[mf][nf][half * 2 + 1] + bz1);
                    size_t off = (size_t)row * F_W + col;
                    if (Cf) {
                        if (row < M) *(float2*)(Cf + off) = make_float2(o0, o1);
                    } else {
                        *(uint32_t*)((char*)Ch + off * 2) = f16x2_rn(o0, o1);
                    }
                }
            }
        }
    }
}

// ---------------- launch ----------------
extern "C" void kernel_launch(void* const* d_in, const int* in_sizes, int n_in,
                              void* d_out, int out_size) {
    const float* v      = (const float*)d_in[0];
    const float* e_rel  = (const float*)d_in[1];
    const void*  idx    = (const void*) d_in[2];
    const float* v_skip = (const float*)d_in[3];
    const float* We     = (const float*)d_in[4];
    const float* be     = (const float*)d_in[5];
    const float* ln_g   = (const float*)d_in[6];
    const float* ln_b   = (const float*)d_in[7];
    const float* W0     = (const float*)d_in[8];
    const float* b0     = (const float*)d_in[9];
    const float* W1     = (const float*)d_in[10];
    const float* b1     = (const float*)d_in[11];
    const float* W2     = (const float*)d_in[12];
    const float* b2     = (const float*)d_in[13];
    const float* W3     = (const float*)d_in[14];
    const float* b3     = (const float*)d_in[15];

    int M = in_sizes[1];  // e_rel element count = N_HR

    __half *a, *b, *w0, *w1, *w2, *w3;
    float *pu, *pc1, *pr, *pc2;
    cudaGetSymbolAddress((void**)&a,  g_a);
    cudaGetSymbolAddress((void**)&b,  g_b);
    cudaGetSymbolAddress((void**)&w0, g_w0);
    cudaGetSymbolAddress((void**)&w1, g_w1);
    cudaGetSymbolAddress((void**)&w2, g_w2);
    cudaGetSymbolAddress((void**)&w3, g_w3);
    cudaGetSymbolAddress((void**)&pu,  g_u);
    cudaGetSymbolAddress((void**)&pc1, g_c1);
    cudaGetSymbolAddress((void**)&pr,  g_r);
    cudaGetSymbolAddress((void**)&pc2, g_c2);

    cudaFuncSetAttribute(gemm_f16_selu,
                         cudaFuncAttributeMaxDynamicSharedMemorySize, GEMM_SMEM);

    int ntot = 4 * F_W * F_W;
    int mpad = ((M + BM - 1) / BM) * BM;
    dim3 grid(F_W / BN, mpad / BM);

    wconv_all_kernel<<<(ntot + 255) / 256, 256>>>((const int*)idx, We, be,
                                                  W0, w0, W1, w1, W2, w2, W3, w3);
    precomp_kernel<<<512, 256>>>(W0, We, be, ln_g, ln_b, b0);
    prep_kernel<<<mpad / 16, 256>>>(v, e_rel, idx, v_skip, ln_g, M);

    gemm_f16_selu<<<grid, 256, GEMM_SMEM>>>(a, w0, nullptr, b, nullptr,
                                            pu, pc1, pr, pc2, M, F_W);
    gemm_f16_selu<<<grid, 256, GEMM_SMEM>>>(b, w1, b1, a, nullptr,
                                            nullptr, nullptr, nullptr, nullptr, M, F_W);
    gemm_f16_selu<<<grid, 256, GEMM_SMEM>>>(a, w2, b2, b, nullptr,
                                            nullptr, nullptr, nullptr, nullptr, M, F_W);
    gemm_f16_selu<<<grid, 256, GEMM_SMEM>>>(b, w3, b3, nullptr, (float*)d_out,
                                            nullptr, nullptr, nullptr, nullptr, M, F_W);
}